// round 6
// baseline (speedup 1.0000x reference)
#include <cuda_runtime.h>
#include <cuda_fp16.h>
#include <cstdint>

// Problem constants
#define NN 50000
#define EE 800000
#define HD 512
#define IND 256
#define OUTD 64

// ---------------- Scratch (static device globals; no allocation APIs) -------
__device__ __align__(16) int    g_src[EE];
__device__ __align__(16) int    g_dst[EE];
__device__ __align__(16) int    g_counts[NN];
__device__ __align__(16) int    g_off[NN + 1];
__device__ __align__(16) int    g_cursor[NN];
__device__ __align__(16) float  g_dinv[NN];
__device__ __align__(16) int    g_csr_src[EE];
__device__ __align__(16) __half g_xw[(size_t)NN * HD];  // 51.2 MB (L2-resident)
__device__ __align__(16) float  g_h[(size_t)NN * HD];   // 102.4 MB
__device__ int g_flag;            // 1 = edge_index stored as int64, 0 = int32
__device__ int g_blocksums[64];

// ---------------- Edge dtype detection --------------------------------------
__global__ void detect_kernel(const int* __restrict__ raw) {
    __shared__ int any;
    if (threadIdx.x == 0) any = 0;
    __syncthreads();
    int v = raw[2 * threadIdx.x + 1];
    if (v != 0) atomicOr(&any, 1);
    __syncthreads();
    if (threadIdx.x == 0) g_flag = any ? 0 : 1;
}

__global__ void zero_counts_kernel() {
    int i = blockIdx.x * blockDim.x + threadIdx.x;
    if (i < NN) { g_counts[i] = 0; g_cursor[i] = 0; }
}

__global__ void convert_edges_kernel(const int* __restrict__ raw) {
    int e = blockIdx.x * blockDim.x + threadIdx.x;
    if (e >= EE) return;
    int s, d;
    if (g_flag) { s = raw[2 * e]; d = raw[2 * (EE + e)]; }
    else        { s = raw[e];     d = raw[EE + e]; }
    g_src[e] = s;
    g_dst[e] = d;
    atomicAdd(&g_counts[d], 1);
}

__global__ void dinv_kernel() {
    int i = blockIdx.x * blockDim.x + threadIdx.x;
    if (i < NN) g_dinv[i] = rsqrtf((float)(g_counts[i] + 1));  // +1 self-loop
}

// ---------------- Exclusive scan of counts -> offsets ------------------------
#define SCAN_BLK 1024
#define SCAN_NBLK ((NN + SCAN_BLK - 1) / SCAN_BLK)   // 49

__global__ void scan1_kernel() {
    __shared__ int s[SCAN_BLK];
    int i = blockIdx.x * SCAN_BLK + threadIdx.x;
    int v = (i < NN) ? g_counts[i] : 0;
    s[threadIdx.x] = v;
    __syncthreads();
    for (int d = 1; d < SCAN_BLK; d <<= 1) {
        int t = (threadIdx.x >= d) ? s[threadIdx.x - d] : 0;
        __syncthreads();
        s[threadIdx.x] += t;
        __syncthreads();
    }
    if (i < NN) g_off[i] = s[threadIdx.x] - v;   // exclusive within block
    if (threadIdx.x == SCAN_BLK - 1) g_blocksums[blockIdx.x] = s[SCAN_BLK - 1];
}

__global__ void scan2_kernel() {
    if (threadIdx.x == 0) {
        int acc = 0;
        for (int b = 0; b < SCAN_NBLK; b++) {
            int t = g_blocksums[b];
            g_blocksums[b] = acc;
            acc += t;
        }
    }
}

__global__ void scan3_kernel() {
    int i = blockIdx.x * SCAN_BLK + threadIdx.x;
    if (i < NN) g_off[i] += g_blocksums[blockIdx.x];
    if (i == 0) g_off[NN] = EE;
}

__global__ void scatter_kernel() {
    int e = blockIdx.x * blockDim.x + threadIdx.x;
    if (e >= EE) return;
    int d = g_dst[e];
    int pos = g_off[d] + atomicAdd(&g_cursor[d], 1);
    g_csr_src[pos] = g_src[e];
}

// ---------------- TF32 tensor-core GEMM (verified round-4 version) -----------
// C[M,N] = A[M,K] @ B[K,N] (+ bias). A,B row-major fp32. K % 32 == 0, N % BN == 0.
// OUT_HALF: write C as fp16. Register-staged 2-stage pipeline.
__device__ __forceinline__ unsigned f2tf32(float x) {
    unsigned r;
    asm("cvt.rna.tf32.f32 %0, %1;" : "=r"(r) : "f"(x));
    return r;
}

template <int BM, int BN, int WARPS_M, int WARPS_N, bool OUT_HALF, bool BIAS>
__global__ __launch_bounds__(WARPS_M * WARPS_N * 32)
void tf32_gemm_kernel(const float* __restrict__ A,
                      const float* __restrict__ B,
                      const float* __restrict__ bias,
                      void* __restrict__ Cv,
                      int M, int N, int K) {
    constexpr int BK = 32;
    constexpr int THREADS = WARPS_M * WARPS_N * 32;
    constexpr int WM = BM / WARPS_M;       // 64
    constexpr int WN = BN / WARPS_N;       // 32
    constexpr int MT = WM / 16;            // 4
    constexpr int NT = WN / 8;             // 4
    constexpr int LDA = BM + 4;            // frag loads conflict-free: 4*tg+g distinct
    constexpr int LDB = BN + 4;
    constexpr int A_F4 = BM * BK / (THREADS * 4);  // float4 per thread (A tile)
    constexpr int B_F4 = BK * BN / (THREADS * 4);

    __shared__ unsigned As[BK * LDA];      // As[k][m], tf32
    __shared__ unsigned Bs[BK * LDB];      // Bs[k][n], tf32

    int tid = threadIdx.x;
    int lane = tid & 31;
    int warp = tid >> 5;
    int g  = lane >> 2;                    // group id 0..7
    int tg = lane & 3;                     // thread in group 0..3
    int wm = warp / WARPS_N;
    int wn = warp % WARPS_N;
    int rowBase = blockIdx.y * BM;
    int colBase = blockIdx.x * BN;
    int m_base = wm * WM;
    int n_base = wn * WN;

    float acc[MT][NT][4];
#pragma unroll
    for (int i = 0; i < MT; i++)
#pragma unroll
        for (int j = 0; j < NT; j++)
#pragma unroll
            for (int r = 0; r < 4; r++) acc[i][j][r] = 0.f;

    float4 ra[A_F4], rb[B_F4];

    auto load_tile = [&](int k0) {
#pragma unroll
        for (int u = 0; u < A_F4; u++) {
            int idx = (tid + u * THREADS) * 4;
            int r = idx / BK, c = idx % BK;
            int grow = rowBase + r;
            ra[u] = (grow < M) ? *(const float4*)(A + (size_t)grow * K + k0 + c)
                               : make_float4(0.f, 0.f, 0.f, 0.f);
        }
#pragma unroll
        for (int u = 0; u < B_F4; u++) {
            int idx = (tid + u * THREADS) * 4;
            int r = idx / BN, c = idx % BN;
            rb[u] = *(const float4*)(B + (size_t)(k0 + r) * N + colBase + c);
        }
    };
    auto store_tile = [&]() {
#pragma unroll
        for (int u = 0; u < A_F4; u++) {
            int idx = (tid + u * THREADS) * 4;
            int r = idx / BK, c = idx % BK;
            As[(c + 0) * LDA + r] = f2tf32(ra[u].x);
            As[(c + 1) * LDA + r] = f2tf32(ra[u].y);
            As[(c + 2) * LDA + r] = f2tf32(ra[u].z);
            As[(c + 3) * LDA + r] = f2tf32(ra[u].w);
        }
#pragma unroll
        for (int u = 0; u < B_F4; u++) {
            int idx = (tid + u * THREADS) * 4;
            int r = idx / BN, c = idx % BN;
            uint4 q;
            q.x = f2tf32(rb[u].x); q.y = f2tf32(rb[u].y);
            q.z = f2tf32(rb[u].z); q.w = f2tf32(rb[u].w);
            *(uint4*)&Bs[r * LDB + c] = q;
        }
    };

    load_tile(0);
    store_tile();
    __syncthreads();

    int nIter = K / BK;
    for (int it = 0; it < nIter; it++) {
        if (it + 1 < nIter) load_tile((it + 1) * BK);   // prefetch (global)

#pragma unroll
        for (int ks = 0; ks < BK / 8; ks++) {
            int k = ks * 8;
            unsigned a[MT][4];
#pragma unroll
            for (int mt = 0; mt < MT; mt++) {
                int m0 = m_base + mt * 16 + g;
                a[mt][0] = As[(k + tg) * LDA + m0];
                a[mt][1] = As[(k + tg) * LDA + m0 + 8];
                a[mt][2] = As[(k + tg + 4) * LDA + m0];
                a[mt][3] = As[(k + tg + 4) * LDA + m0 + 8];
            }
            unsigned b[NT][2];
#pragma unroll
            for (int nt = 0; nt < NT; nt++) {
                int n0 = n_base + nt * 8 + g;
                b[nt][0] = Bs[(k + tg) * LDB + n0];
                b[nt][1] = Bs[(k + tg + 4) * LDB + n0];
            }
#pragma unroll
            for (int mt = 0; mt < MT; mt++)
#pragma unroll
                for (int nt = 0; nt < NT; nt++) {
                    asm volatile(
                        "mma.sync.aligned.m16n8k8.row.col.f32.tf32.tf32.f32 "
                        "{%0,%1,%2,%3}, {%4,%5,%6,%7}, {%8,%9}, {%0,%1,%2,%3};"
                        : "+f"(acc[mt][nt][0]), "+f"(acc[mt][nt][1]),
                          "+f"(acc[mt][nt][2]), "+f"(acc[mt][nt][3])
                        : "r"(a[mt][0]), "r"(a[mt][1]), "r"(a[mt][2]), "r"(a[mt][3]),
                          "r"(b[nt][0]), "r"(b[nt][1]));
                }
        }
        __syncthreads();
        if (it + 1 < nIter) {
            store_tile();
            __syncthreads();
        }
    }

    // Epilogue
#pragma unroll
    for (int mt = 0; mt < MT; mt++) {
#pragma unroll
        for (int nt = 0; nt < NT; nt++) {
            int row0 = rowBase + m_base + mt * 16 + g;
            int col  = colBase + n_base + nt * 8 + 2 * tg;
            float2 v0 = make_float2(acc[mt][nt][0], acc[mt][nt][1]);
            float2 v1 = make_float2(acc[mt][nt][2], acc[mt][nt][3]);
            if constexpr (BIAS) {
                float2 bv = *(const float2*)(bias + col);
                v0.x += bv.x; v0.y += bv.y;
                v1.x += bv.x; v1.y += bv.y;
            }
            if constexpr (OUT_HALF) {
                __half* C = (__half*)Cv;
                if (row0 < M)
                    *(__half2*)(C + (size_t)row0 * N + col) = __floats2half2_rn(v0.x, v0.y);
                if (row0 + 8 < M)
                    *(__half2*)(C + (size_t)(row0 + 8) * N + col) = __floats2half2_rn(v1.x, v1.y);
            } else {
                float* C = (float*)Cv;
                if (row0 < M)     *(float2*)(C + (size_t)row0 * N + col) = v0;
                if (row0 + 8 < M) *(float2*)(C + (size_t)(row0 + 8) * N + col) = v1;
            }
        }
    }
}

// ---------------- Gather aggregation: 2 warps per node (256 feats each) ------
// out = relu(sum_{s in N(i)} w_si * xw[s] + dii*xw[i] + bias), fp32 accum/out.
__global__ void aggregate_kernel(const __half* __restrict__ xw,
                                 const float* __restrict__ bias,
                                 float* __restrict__ out) {
    int gwarp = (blockIdx.x * blockDim.x + threadIdx.x) >> 5;
    int lane = threadIdx.x & 31;
    int i = gwarp >> 1;            // node
    int half = gwarp & 1;          // which 256-feature half
    if (i >= NN) return;

    int fb = half * 32 + lane;     // uint4 index within row (0..63)

    float di = g_dinv[i];
    float self = di * di;

    float acc[8];
    {
        uint4 v = ((const uint4*)(xw + (size_t)i * HD))[fb];
        const __half2* h2 = (const __half2*)&v;
        const float4* b4 = (const float4*)(bias + 8 * fb);
        float4 b0 = b4[0], b1 = b4[1];
        float2 f0 = __half22float2(h2[0]);
        float2 f1 = __half22float2(h2[1]);
        float2 f2 = __half22float2(h2[2]);
        float2 f3 = __half22float2(h2[3]);
        acc[0] = fmaf(f0.x, self, b0.x);
        acc[1] = fmaf(f0.y, self, b0.y);
        acc[2] = fmaf(f1.x, self, b0.z);
        acc[3] = fmaf(f1.y, self, b0.w);
        acc[4] = fmaf(f2.x, self, b1.x);
        acc[5] = fmaf(f2.y, self, b1.y);
        acc[6] = fmaf(f3.x, self, b1.z);
        acc[7] = fmaf(f3.y, self, b1.w);
    }

    int beg = g_off[i];
    int cnt = g_counts[i];
    for (int t = 0; t < cnt; t++) {
        int s = g_csr_src[beg + t];
        float w = g_dinv[s] * di;
        uint4 v = ((const uint4*)(xw + (size_t)s * HD))[fb];
        const __half2* h2 = (const __half2*)&v;
#pragma unroll
        for (int q = 0; q < 4; q++) {
            float2 f = __half22float2(h2[q]);
            acc[2 * q + 0] = fmaf(f.x, w, acc[2 * q + 0]);
            acc[2 * q + 1] = fmaf(f.y, w, acc[2 * q + 1]);
        }
    }

    float4* orow = (float4*)(out + (size_t)i * HD + 8 * fb);
    float4 o0, o1;
    o0.x = fmaxf(acc[0], 0.f); o0.y = fmaxf(acc[1], 0.f);
    o0.z = fmaxf(acc[2], 0.f); o0.w = fmaxf(acc[3], 0.f);
    o1.x = fmaxf(acc[4], 0.f); o1.y = fmaxf(acc[5], 0.f);
    o1.z = fmaxf(acc[6], 0.f); o1.w = fmaxf(acc[7], 0.f);
    orow[0] = o0;
    orow[1] = o1;
}

// ---------------- Launch -----------------------------------------------------
extern "C" void kernel_launch(void* const* d_in, const int* in_sizes, int n_in,
                              void* d_out, int out_size) {
    const float* x  = (const float*)d_in[0];
    const int*   ei = (const int*)d_in[1];   // int32 OR int64, detected on device
    const float* W1 = (const float*)d_in[2];
    const float* b1 = (const float*)d_in[3];
    const float* W2 = (const float*)d_in[4];
    const float* b2 = (const float*)d_in[5];
    const float* Wl = (const float*)d_in[6];
    const float* bl = (const float*)d_in[7];
    float* out = (float*)d_out;

    __half* xw; cudaGetSymbolAddress((void**)&xw, g_xw);
    float*  h;  cudaGetSymbolAddress((void**)&h,  g_h);

    // Graph prep
    detect_kernel<<<1, 256>>>(ei);
    zero_counts_kernel<<<(NN + 255) / 256, 256>>>();
    convert_edges_kernel<<<(EE + 255) / 256, 256>>>(ei);
    dinv_kernel<<<(NN + 255) / 256, 256>>>();
    scan1_kernel<<<SCAN_NBLK, SCAN_BLK>>>();
    scan2_kernel<<<1, 32>>>();
    scan3_kernel<<<SCAN_NBLK, SCAN_BLK>>>();
    scatter_kernel<<<(EE + 255) / 256, 256>>>();

    int aggBlocks = (NN * 2 * 32 + 255) / 256;   // 2 warps per node

    // Layer 1: xw = fp16(x @ W1) ; h = relu(aggregate(xw) + b1)
    {
        dim3 grid(HD / 128, (NN + 127) / 128);
        tf32_gemm_kernel<128, 128, 2, 4, true, false><<<grid, 256>>>(x, W1, nullptr, xw, NN, HD, IND);
        aggregate_kernel<<<aggBlocks, 256>>>(xw, b1, h);
    }
    // Layer 2: xw = fp16(h @ W2) ; h = relu(aggregate(xw) + b2)
    {
        dim3 grid(HD / 128, (NN + 127) / 128);
        tf32_gemm_kernel<128, 128, 2, 4, true, false><<<grid, 256>>>(h, W2, nullptr, xw, NN, HD, HD);
        aggregate_kernel<<<aggBlocks, 256>>>(xw, b2, h);
    }
    // Output: out = h @ Wl + bl (fp32)
    {
        dim3 grid(OUTD / 64, (NN + 127) / 128);
        tf32_gemm_kernel<128, 64, 2, 2, false, true><<<grid, 128>>>(h, Wl, bl, out, NN, OUTD, HD);
    }
}

// round 7
// speedup vs baseline: 1.6277x; 1.6277x over previous
#include <cuda_runtime.h>
#include <cuda_fp16.h>
#include <cstdint>

// Problem constants
#define NN 50000
#define EE 800000
#define HD 512
#define IND 256
#define OUTD 64

// ---------------- Scratch (static device globals; no allocation APIs) -------
__device__ __align__(16) int    g_src[EE];
__device__ __align__(16) int    g_dst[EE];
__device__ __align__(16) int    g_counts[NN];
__device__ __align__(16) int    g_off[NN + 1];
__device__ __align__(16) int    g_cursor[NN];
__device__ __align__(16) float  g_dinv[NN];
__device__ __align__(16) int    g_csr_src[EE];
__device__ __align__(16) __half g_xw[(size_t)NN * HD];  // 51.2 MB (L2-resident)
__device__ __align__(16) __half g_h[(size_t)NN * HD];   // 51.2 MB (L2-resident)
__device__ int g_flag;            // 1 = edge_index stored as int64, 0 = int32
__device__ int g_blocksums[64];

// ---------------- Edge dtype detection --------------------------------------
__global__ void detect_kernel(const int* __restrict__ raw) {
    __shared__ int any;
    if (threadIdx.x == 0) any = 0;
    __syncthreads();
    int v = raw[2 * threadIdx.x + 1];
    if (v != 0) atomicOr(&any, 1);
    __syncthreads();
    if (threadIdx.x == 0) g_flag = any ? 0 : 1;
}

__global__ void zero_counts_kernel() {
    int i = blockIdx.x * blockDim.x + threadIdx.x;
    if (i < NN) { g_counts[i] = 0; g_cursor[i] = 0; }
}

__global__ void convert_edges_kernel(const int* __restrict__ raw) {
    int e = blockIdx.x * blockDim.x + threadIdx.x;
    if (e >= EE) return;
    int s, d;
    if (g_flag) { s = raw[2 * e]; d = raw[2 * (EE + e)]; }
    else        { s = raw[e];     d = raw[EE + e]; }
    g_src[e] = s;
    g_dst[e] = d;
    atomicAdd(&g_counts[d], 1);
}

__global__ void dinv_kernel() {
    int i = blockIdx.x * blockDim.x + threadIdx.x;
    if (i < NN) g_dinv[i] = rsqrtf((float)(g_counts[i] + 1));  // +1 self-loop
}

// ---------------- Exclusive scan of counts -> offsets ------------------------
#define SCAN_BLK 1024
#define SCAN_NBLK ((NN + SCAN_BLK - 1) / SCAN_BLK)   // 49

__global__ void scan1_kernel() {
    __shared__ int s[SCAN_BLK];
    int i = blockIdx.x * SCAN_BLK + threadIdx.x;
    int v = (i < NN) ? g_counts[i] : 0;
    s[threadIdx.x] = v;
    __syncthreads();
    for (int d = 1; d < SCAN_BLK; d <<= 1) {
        int t = (threadIdx.x >= d) ? s[threadIdx.x - d] : 0;
        __syncthreads();
        s[threadIdx.x] += t;
        __syncthreads();
    }
    if (i < NN) g_off[i] = s[threadIdx.x] - v;   // exclusive within block
    if (threadIdx.x == SCAN_BLK - 1) g_blocksums[blockIdx.x] = s[SCAN_BLK - 1];
}

__global__ void scan2_kernel() {
    if (threadIdx.x == 0) {
        int acc = 0;
        for (int b = 0; b < SCAN_NBLK; b++) {
            int t = g_blocksums[b];
            g_blocksums[b] = acc;
            acc += t;
        }
    }
}

__global__ void scan3_kernel() {
    int i = blockIdx.x * SCAN_BLK + threadIdx.x;
    if (i < NN) g_off[i] += g_blocksums[blockIdx.x];
    if (i == 0) g_off[NN] = EE;
}

__global__ void scatter_kernel() {
    int e = blockIdx.x * blockDim.x + threadIdx.x;
    if (e >= EE) return;
    int d = g_dst[e];
    int pos = g_off[d] + atomicAdd(&g_cursor[d], 1);
    g_csr_src[pos] = g_src[e];
}

// ---------------- FP16 tensor-core GEMM (fp32 accumulate) --------------------
// C[M,N] = A[M,K] @ B[K,N] (+ bias). B row-major fp32 (converted to fp16 in
// smem). A fp32 (converted) or fp16. OUT_HALF: C as fp16.
// As[m][k], Bs[n][k], LDK = BK+8 = 40 -> 32 distinct banks on fragment loads.
// Each loader thread covers 8 halves (one uint4 in As / two float4 in gmem).
template <int BM, int BN, int WARPS_M, int WARPS_N, bool A_HALF, bool OUT_HALF, bool BIAS>
__global__ __launch_bounds__(WARPS_M * WARPS_N * 32)
void h_gemm_kernel(const void* __restrict__ Av,
                   const float* __restrict__ B,
                   const float* __restrict__ bias,
                   void* __restrict__ Cv,
                   int M, int N, int K) {
    constexpr int BK = 32;                  // k-tile (halves)
    constexpr int THREADS = WARPS_M * WARPS_N * 32;
    constexpr int WM = BM / WARPS_M;        // 64
    constexpr int WN = BN / WARPS_N;        // 32
    constexpr int MT = WM / 16;             // 4
    constexpr int NT = WN / 8;              // 4
    constexpr int LDK = BK + 8;             // 40 halves/row
    constexpr int A_ITER = BM * BK / (THREADS * 8);  // 8 halves per thread per iter
    constexpr int KG = THREADS / BN;        // k-groups per B pass
    constexpr int B_PASS = BK / (KG * 4);

    __shared__ __half As[BM * LDK];
    __shared__ __half Bs[BN * LDK];

    int tid = threadIdx.x;
    int lane = tid & 31;
    int warp = tid >> 5;
    int g  = lane >> 2;                     // 0..7
    int tg = lane & 3;                      // 0..3
    int wm = warp / WARPS_N;
    int wn = warp % WARPS_N;
    int rowBase = blockIdx.y * BM;
    int colBase = blockIdx.x * BN;
    int m_base = wm * WM;
    int n_base = wn * WN;

    float acc[MT][NT][4];
#pragma unroll
    for (int i = 0; i < MT; i++)
#pragma unroll
        for (int j = 0; j < NT; j++)
#pragma unroll
            for (int r = 0; r < 4; r++) acc[i][j][r] = 0.f;

    // Prefetch registers: per iter, 8 halves (A_HALF: one uint4; else two float4)
    uint4  raH[A_HALF ? A_ITER : 1];
    float4 raF[A_HALF ? 1 : 2 * A_ITER];
    float  rbF[B_PASS][4];
    int b_n = tid % BN;                     // B column for this thread
    int b_kg = (tid / BN) * 4;              // k offset within 8-group

    auto load_tile = [&](int k0) {
#pragma unroll
        for (int u = 0; u < A_ITER; u++) {
            int off = (tid + u * THREADS) * 8;   // halves
            int r = off / BK, c = off % BK;
            int grow = rowBase + r;
            if constexpr (A_HALF) {
                const __half* A = (const __half*)Av;
                raH[u] = (grow < M) ? *(const uint4*)(A + (size_t)grow * K + k0 + c)
                                    : make_uint4(0, 0, 0, 0);
            } else {
                const float* A = (const float*)Av;
                if (grow < M) {
                    raF[2 * u + 0] = *(const float4*)(A + (size_t)grow * K + k0 + c);
                    raF[2 * u + 1] = *(const float4*)(A + (size_t)grow * K + k0 + c + 4);
                } else {
                    raF[2 * u + 0] = make_float4(0.f, 0.f, 0.f, 0.f);
                    raF[2 * u + 1] = make_float4(0.f, 0.f, 0.f, 0.f);
                }
            }
        }
#pragma unroll
        for (int p = 0; p < B_PASS; p++) {
            int kk = p * (KG * 4) + b_kg;
#pragma unroll
            for (int j = 0; j < 4; j++)
                rbF[p][j] = B[(size_t)(k0 + kk + j) * N + colBase + b_n];
        }
    };
    auto store_tile = [&]() {
#pragma unroll
        for (int u = 0; u < A_ITER; u++) {
            int off = (tid + u * THREADS) * 8;
            int r = off / BK, c = off % BK;
            if constexpr (A_HALF) {
                *(uint4*)(As + r * LDK + c) = raH[u];
            } else {
                __half2 h0 = __floats2half2_rn(raF[2 * u].x, raF[2 * u].y);
                __half2 h1 = __floats2half2_rn(raF[2 * u].z, raF[2 * u].w);
                __half2 h2 = __floats2half2_rn(raF[2 * u + 1].x, raF[2 * u + 1].y);
                __half2 h3 = __floats2half2_rn(raF[2 * u + 1].z, raF[2 * u + 1].w);
                uint4 q;
                q.x = *(unsigned*)&h0; q.y = *(unsigned*)&h1;
                q.z = *(unsigned*)&h2; q.w = *(unsigned*)&h3;
                *(uint4*)(As + r * LDK + c) = q;
            }
        }
#pragma unroll
        for (int p = 0; p < B_PASS; p++) {
            int kk = p * (KG * 4) + b_kg;
            __half2 h0 = __floats2half2_rn(rbF[p][0], rbF[p][1]);
            __half2 h1 = __floats2half2_rn(rbF[p][2], rbF[p][3]);
            uint2 q;
            q.x = *(unsigned*)&h0; q.y = *(unsigned*)&h1;
            *(uint2*)(Bs + b_n * LDK + kk) = q;   // transposed store [n][k]
        }
    };

    load_tile(0);
    store_tile();
    __syncthreads();

    int nIter = K / BK;
    for (int it = 0; it < nIter; it++) {
        if (it + 1 < nIter) load_tile((it + 1) * BK);

#pragma unroll
        for (int ks = 0; ks < BK / 16; ks++) {
            int k = ks * 16;
            unsigned a[MT][4];
#pragma unroll
            for (int mt = 0; mt < MT; mt++) {
                int m0 = m_base + mt * 16 + g;
                a[mt][0] = *(const unsigned*)(As + m0 * LDK + k + 2 * tg);
                a[mt][1] = *(const unsigned*)(As + (m0 + 8) * LDK + k + 2 * tg);
                a[mt][2] = *(const unsigned*)(As + m0 * LDK + k + 2 * tg + 8);
                a[mt][3] = *(const unsigned*)(As + (m0 + 8) * LDK + k + 2 * tg + 8);
            }
            unsigned b[NT][2];
#pragma unroll
            for (int nt = 0; nt < NT; nt++) {
                int n0 = n_base + nt * 8 + g;
                b[nt][0] = *(const unsigned*)(Bs + n0 * LDK + k + 2 * tg);
                b[nt][1] = *(const unsigned*)(Bs + n0 * LDK + k + 2 * tg + 8);
            }
#pragma unroll
            for (int mt = 0; mt < MT; mt++)
#pragma unroll
                for (int nt = 0; nt < NT; nt++) {
                    asm volatile(
                        "mma.sync.aligned.m16n8k16.row.col.f32.f16.f16.f32 "
                        "{%0,%1,%2,%3}, {%4,%5,%6,%7}, {%8,%9}, {%0,%1,%2,%3};"
                        : "+f"(acc[mt][nt][0]), "+f"(acc[mt][nt][1]),
                          "+f"(acc[mt][nt][2]), "+f"(acc[mt][nt][3])
                        : "r"(a[mt][0]), "r"(a[mt][1]), "r"(a[mt][2]), "r"(a[mt][3]),
                          "r"(b[nt][0]), "r"(b[nt][1]));
                }
        }
        __syncthreads();
        if (it + 1 < nIter) {
            store_tile();
            __syncthreads();
        }
    }

    // Epilogue (c-fragment layout: c0,c1 -> row g col 2tg; c2,c3 -> row g+8)
#pragma unroll
    for (int mt = 0; mt < MT; mt++) {
#pragma unroll
        for (int nt = 0; nt < NT; nt++) {
            int row0 = rowBase + m_base + mt * 16 + g;
            int col  = colBase + n_base + nt * 8 + 2 * tg;
            float2 v0 = make_float2(acc[mt][nt][0], acc[mt][nt][1]);
            float2 v1 = make_float2(acc[mt][nt][2], acc[mt][nt][3]);
            if constexpr (BIAS) {
                float2 bv = *(const float2*)(bias + col);
                v0.x += bv.x; v0.y += bv.y;
                v1.x += bv.x; v1.y += bv.y;
            }
            if constexpr (OUT_HALF) {
                __half* C = (__half*)Cv;
                if (row0 < M)
                    *(__half2*)(C + (size_t)row0 * N + col) = __floats2half2_rn(v0.x, v0.y);
                if (row0 + 8 < M)
                    *(__half2*)(C + (size_t)(row0 + 8) * N + col) = __floats2half2_rn(v1.x, v1.y);
            } else {
                float* C = (float*)Cv;
                if (row0 < M)     *(float2*)(C + (size_t)row0 * N + col) = v0;
                if (row0 + 8 < M) *(float2*)(C + (size_t)(row0 + 8) * N + col) = v1;
            }
        }
    }
}

// ---------------- Gather aggregation (warp per node), fp16 in / fp16 out -----
__global__ void aggregate_kernel(const __half* __restrict__ xw,
                                 const float* __restrict__ bias,
                                 __half* __restrict__ out) {
    int warp = (blockIdx.x * blockDim.x + threadIdx.x) >> 5;
    int lane = threadIdx.x & 31;
    if (warp >= NN) return;
    int i = warp;

    float di = g_dinv[i];
    float self = di * di;

    float acc[2][8];
    {
        const uint4* xrow = (const uint4*)(xw + (size_t)i * HD);
#pragma unroll
        for (int c = 0; c < 2; c++) {
            uint4 v = xrow[lane + 32 * c];
            const __half2* h2 = (const __half2*)&v;
            const float4* b4 = (const float4*)(bias + 8 * (lane + 32 * c));
            float4 b0 = b4[0], b1 = b4[1];
            float2 f0 = __half22float2(h2[0]);
            float2 f1 = __half22float2(h2[1]);
            float2 f2 = __half22float2(h2[2]);
            float2 f3 = __half22float2(h2[3]);
            acc[c][0] = fmaf(f0.x, self, b0.x);
            acc[c][1] = fmaf(f0.y, self, b0.y);
            acc[c][2] = fmaf(f1.x, self, b0.z);
            acc[c][3] = fmaf(f1.y, self, b0.w);
            acc[c][4] = fmaf(f2.x, self, b1.x);
            acc[c][5] = fmaf(f2.y, self, b1.y);
            acc[c][6] = fmaf(f3.x, self, b1.z);
            acc[c][7] = fmaf(f3.y, self, b1.w);
        }
    }

    int beg = g_off[i];
    int cnt = g_counts[i];
    for (int t = 0; t < cnt; t++) {
        int s = g_csr_src[beg + t];
        float w = g_dinv[s] * di;
        const uint4* srow = (const uint4*)(xw + (size_t)s * HD);
        uint4 v0 = srow[lane];
        uint4 v1 = srow[lane + 32];
#pragma unroll
        for (int c = 0; c < 2; c++) {
            uint4 v = c ? v1 : v0;
            const __half2* h2 = (const __half2*)&v;
#pragma unroll
            for (int q = 0; q < 4; q++) {
                float2 f = __half22float2(h2[q]);
                acc[c][2 * q + 0] = fmaf(f.x, w, acc[c][2 * q + 0]);
                acc[c][2 * q + 1] = fmaf(f.y, w, acc[c][2 * q + 1]);
            }
        }
    }

#pragma unroll
    for (int c = 0; c < 2; c++) {
        __half2 h0 = __floats2half2_rn(fmaxf(acc[c][0], 0.f), fmaxf(acc[c][1], 0.f));
        __half2 h1 = __floats2half2_rn(fmaxf(acc[c][2], 0.f), fmaxf(acc[c][3], 0.f));
        __half2 h2 = __floats2half2_rn(fmaxf(acc[c][4], 0.f), fmaxf(acc[c][5], 0.f));
        __half2 h3 = __floats2half2_rn(fmaxf(acc[c][6], 0.f), fmaxf(acc[c][7], 0.f));
        uint4 q;
        q.x = *(unsigned*)&h0; q.y = *(unsigned*)&h1;
        q.z = *(unsigned*)&h2; q.w = *(unsigned*)&h3;
        *(uint4*)(out + (size_t)i * HD + 8 * (lane + 32 * c)) = q;
    }
}

// ---------------- Launch -----------------------------------------------------
extern "C" void kernel_launch(void* const* d_in, const int* in_sizes, int n_in,
                              void* d_out, int out_size) {
    const float* x  = (const float*)d_in[0];
    const int*   ei = (const int*)d_in[1];   // int32 OR int64, detected on device
    const float* W1 = (const float*)d_in[2];
    const float* b1 = (const float*)d_in[3];
    const float* W2 = (const float*)d_in[4];
    const float* b2 = (const float*)d_in[5];
    const float* Wl = (const float*)d_in[6];
    const float* bl = (const float*)d_in[7];
    float* out = (float*)d_out;

    __half* xw; cudaGetSymbolAddress((void**)&xw, g_xw);
    __half* h;  cudaGetSymbolAddress((void**)&h,  g_h);

    // Graph prep
    detect_kernel<<<1, 256>>>(ei);
    zero_counts_kernel<<<(NN + 255) / 256, 256>>>();
    convert_edges_kernel<<<(EE + 255) / 256, 256>>>(ei);
    dinv_kernel<<<(NN + 255) / 256, 256>>>();
    scan1_kernel<<<SCAN_NBLK, SCAN_BLK>>>();
    scan2_kernel<<<1, 32>>>();
    scan3_kernel<<<SCAN_NBLK, SCAN_BLK>>>();
    scatter_kernel<<<(EE + 255) / 256, 256>>>();

    // Layer 1: xw = fp16(x @ W1) ; h = fp16(relu(aggregate(xw) + b1))
    {
        dim3 grid(HD / 128, (NN + 127) / 128);
        h_gemm_kernel<128, 128, 2, 4, false, true, false><<<grid, 256>>>(x, W1, nullptr, xw, NN, HD, IND);
        aggregate_kernel<<<(NN * 32 + 255) / 256, 256>>>(xw, b1, h);
    }
    // Layer 2: xw = fp16(h @ W2) ; h = fp16(relu(aggregate(xw) + b2))
    {
        dim3 grid(HD / 128, (NN + 127) / 128);
        h_gemm_kernel<128, 128, 2, 4, true, true, false><<<grid, 256>>>(h, W2, nullptr, xw, NN, HD, HD);
        aggregate_kernel<<<(NN * 32 + 255) / 256, 256>>>(xw, b2, h);
    }
    // Output: out = h @ Wl + bl (fp32 out)
    {
        dim3 grid(OUTD / 64, (NN + 127) / 128);
        h_gemm_kernel<128, 64, 2, 2, true, false, true><<<grid, 128>>>(h, Wl, bl, out, NN, OUTD, HD);
    }
}

// round 8
// speedup vs baseline: 1.9386x; 1.1910x over previous
#include <cuda_runtime.h>
#include <cuda_fp16.h>
#include <cstdint>

// Problem constants
#define NN 50000
#define EE 800000
#define HD 512
#define IND 256
#define OUTD 64

// ---------------- Scratch (static device globals; no allocation APIs) -------
__device__ __align__(16) int    g_src[EE];
__device__ __align__(16) int    g_dst[EE];
__device__ __align__(16) int    g_counts[NN];
__device__ __align__(16) int    g_off[NN + 1];
__device__ __align__(16) int    g_cursor[NN];
__device__ __align__(16) float  g_dinv[NN];
__device__ __align__(16) int    g_csr_src[EE];
__device__ __align__(16) __half g_x16[(size_t)NN * IND];   // 25.6 MB fp16 x
__device__ __align__(16) __half g_w1t[(size_t)HD * IND];   // W1^T [N,K] fp16
__device__ __align__(16) __half g_w2t[(size_t)HD * HD];    // W2^T
__device__ __align__(16) __half g_wlt[(size_t)OUTD * HD];  // Wl^T
__device__ __align__(16) __half g_xw[(size_t)NN * HD];     // 51.2 MB (dinv-scaled)
__device__ __align__(16) __half g_h[(size_t)NN * HD];      // 51.2 MB
__device__ int g_flag;            // 1 = edge_index stored as int64, 0 = int32
__device__ int g_blocksums[64];

// ---------------- Edge dtype detection --------------------------------------
__global__ void detect_kernel(const int* __restrict__ raw) {
    __shared__ int any;
    if (threadIdx.x == 0) any = 0;
    __syncthreads();
    int v = raw[2 * threadIdx.x + 1];
    if (v != 0) atomicOr(&any, 1);
    __syncthreads();
    if (threadIdx.x == 0) g_flag = any ? 0 : 1;
}

__global__ void zero_counts_kernel() {
    int i = blockIdx.x * blockDim.x + threadIdx.x;
    if (i < NN) { g_counts[i] = 0; g_cursor[i] = 0; }
}

__global__ void convert_edges_kernel(const int* __restrict__ raw) {
    int e = blockIdx.x * blockDim.x + threadIdx.x;
    if (e >= EE) return;
    int s, d;
    if (g_flag) { s = raw[2 * e]; d = raw[2 * (EE + e)]; }
    else        { s = raw[e];     d = raw[EE + e]; }
    g_src[e] = s;
    g_dst[e] = d;
    atomicAdd(&g_counts[d], 1);
}

__global__ void dinv_kernel() {
    int i = blockIdx.x * blockDim.x + threadIdx.x;
    if (i < NN) g_dinv[i] = rsqrtf((float)(g_counts[i] + 1));  // +1 self-loop
}

// x fp32 -> fp16 (vectorized: 4 floats per thread)
__global__ void convert_x_kernel(const float* __restrict__ x) {
    int i = blockIdx.x * blockDim.x + threadIdx.x;
    if (i * 4 >= NN * IND) return;
    float4 v = *(const float4*)(x + i * 4);
    __half2 h0 = __floats2half2_rn(v.x, v.y);
    __half2 h1 = __floats2half2_rn(v.z, v.w);
    uint2 q;
    q.x = *(unsigned*)&h0; q.y = *(unsigned*)&h1;
    *(uint2*)(g_x16 + i * 4) = q;
}

// Weight transpose+convert: dst[n*K+k] = fp16(src[k*N+n])
__global__ void transpose_w_kernel(__half* __restrict__ dst,
                                   const float* __restrict__ src,
                                   int K, int N) {
    int i = blockIdx.x * blockDim.x + threadIdx.x;
    if (i >= K * N) return;
    int n = i / K, k = i % K;
    dst[i] = __float2half(src[(size_t)k * N + n]);
}

// ---------------- Exclusive scan of counts -> offsets ------------------------
#define SCAN_BLK 1024
#define SCAN_NBLK ((NN + SCAN_BLK - 1) / SCAN_BLK)   // 49

__global__ void scan1_kernel() {
    __shared__ int s[SCAN_BLK];
    int i = blockIdx.x * SCAN_BLK + threadIdx.x;
    int v = (i < NN) ? g_counts[i] : 0;
    s[threadIdx.x] = v;
    __syncthreads();
    for (int d = 1; d < SCAN_BLK; d <<= 1) {
        int t = (threadIdx.x >= d) ? s[threadIdx.x - d] : 0;
        __syncthreads();
        s[threadIdx.x] += t;
        __syncthreads();
    }
    if (i < NN) g_off[i] = s[threadIdx.x] - v;
    if (threadIdx.x == SCAN_BLK - 1) g_blocksums[blockIdx.x] = s[SCAN_BLK - 1];
}

__global__ void scan2_kernel() {
    if (threadIdx.x == 0) {
        int acc = 0;
        for (int b = 0; b < SCAN_NBLK; b++) {
            int t = g_blocksums[b];
            g_blocksums[b] = acc;
            acc += t;
        }
    }
}

__global__ void scan3_kernel() {
    int i = blockIdx.x * SCAN_BLK + threadIdx.x;
    if (i < NN) g_off[i] += g_blocksums[blockIdx.x];
    if (i == 0) g_off[NN] = EE;
}

__global__ void scatter_kernel() {
    int e = blockIdx.x * blockDim.x + threadIdx.x;
    if (e >= EE) return;
    int d = g_dst[e];
    int pos = g_off[d] + atomicAdd(&g_cursor[d], 1);
    g_csr_src[pos] = g_src[e];
}

// ---------------- cp.async helpers -------------------------------------------
__device__ __forceinline__ void cp_async16(void* smem, const void* gmem, int src_bytes) {
    unsigned saddr = (unsigned)__cvta_generic_to_shared(smem);
    asm volatile("cp.async.cg.shared.global [%0], [%1], 16, %2;\n"
                 :: "r"(saddr), "l"(gmem), "r"(src_bytes));
}
__device__ __forceinline__ void cp_commit() {
    asm volatile("cp.async.commit_group;\n");
}
template <int N>
__device__ __forceinline__ void cp_wait() {
    asm volatile("cp.async.wait_group %0;\n" :: "n"(N));
}

// ---------------- FP16 tensor-core GEMM, cp.async 2-stage --------------------
// C[M,N] = A[M,K] @ B^T (+ bias). A fp16 [M,K] row-major, Bt fp16 [N,K]
// row-major. OUT_HALF: C fp16. SCALE: multiply row r of C by g_dinv[r].
// As[m][k], Bs[n][k], LDK = 40 -> conflict-free fragment loads (verified).
template <int BM, int BN, int WARPS_M, int WARPS_N, bool OUT_HALF, bool BIAS, bool SCALE>
__global__ __launch_bounds__(WARPS_M * WARPS_N * 32)
void h_gemm_kernel(const __half* __restrict__ A,
                   const __half* __restrict__ Bt,
                   const float* __restrict__ bias,
                   void* __restrict__ Cv,
                   int M, int N, int K) {
    constexpr int BK = 32;
    constexpr int THREADS = WARPS_M * WARPS_N * 32;
    constexpr int WM = BM / WARPS_M;        // 64
    constexpr int WN = BN / WARPS_N;        // 32
    constexpr int MT = WM / 16;             // 4
    constexpr int NT = WN / 8;              // 4
    constexpr int LDK = BK + 8;             // 40
    constexpr int CH_A = BM * BK / (8 * THREADS);   // 16B chunks per thread (A)
    constexpr int CH_B = BN * BK / (8 * THREADS);

    __shared__ __half As[2][BM * LDK];
    __shared__ __half Bs[2][BN * LDK];

    int tid = threadIdx.x;
    int lane = tid & 31;
    int warp = tid >> 5;
    int g  = lane >> 2;
    int tg = lane & 3;
    int wm = warp / WARPS_N;
    int wn = warp % WARPS_N;
    int rowBase = blockIdx.y * BM;
    int colBase = blockIdx.x * BN;
    int m_base = wm * WM;
    int n_base = wn * WN;

    float acc[MT][NT][4];
#pragma unroll
    for (int i = 0; i < MT; i++)
#pragma unroll
        for (int j = 0; j < NT; j++)
#pragma unroll
            for (int r = 0; r < 4; r++) acc[i][j][r] = 0.f;

    auto prefetch = [&](int it, int buf) {
        int k0 = it * BK;
#pragma unroll
        for (int u = 0; u < CH_A; u++) {
            int off = (tid + u * THREADS) * 8;
            int r = off / BK, c = off % BK;
            int grow = rowBase + r;
            cp_async16(&As[buf][r * LDK + c],
                       A + (size_t)grow * K + k0 + c,
                       grow < M ? 16 : 0);
        }
#pragma unroll
        for (int u = 0; u < CH_B; u++) {
            int off = (tid + u * THREADS) * 8;
            int r = off / BK, c = off % BK;
            cp_async16(&Bs[buf][r * LDK + c],
                       Bt + (size_t)(colBase + r) * K + k0 + c, 16);
        }
    };

    int nIter = K / BK;
    prefetch(0, 0); cp_commit();
    if (nIter > 1) prefetch(1, 1);
    cp_commit();

    for (int it = 0; it < nIter; it++) {
        cp_wait<1>();
        __syncthreads();
        int buf = it & 1;

#pragma unroll
        for (int ks = 0; ks < BK / 16; ks++) {
            int k = ks * 16;
            unsigned a[MT][4];
#pragma unroll
            for (int mt = 0; mt < MT; mt++) {
                int m0 = m_base + mt * 16 + g;
                a[mt][0] = *(const unsigned*)(&As[buf][m0 * LDK + k + 2 * tg]);
                a[mt][1] = *(const unsigned*)(&As[buf][(m0 + 8) * LDK + k + 2 * tg]);
                a[mt][2] = *(const unsigned*)(&As[buf][m0 * LDK + k + 2 * tg + 8]);
                a[mt][3] = *(const unsigned*)(&As[buf][(m0 + 8) * LDK + k + 2 * tg + 8]);
            }
            unsigned b[NT][2];
#pragma unroll
            for (int nt = 0; nt < NT; nt++) {
                int n0 = n_base + nt * 8 + g;
                b[nt][0] = *(const unsigned*)(&Bs[buf][n0 * LDK + k + 2 * tg]);
                b[nt][1] = *(const unsigned*)(&Bs[buf][n0 * LDK + k + 2 * tg + 8]);
            }
#pragma unroll
            for (int mt = 0; mt < MT; mt++)
#pragma unroll
                for (int nt = 0; nt < NT; nt++) {
                    asm volatile(
                        "mma.sync.aligned.m16n8k16.row.col.f32.f16.f16.f32 "
                        "{%0,%1,%2,%3}, {%4,%5,%6,%7}, {%8,%9}, {%0,%1,%2,%3};"
                        : "+f"(acc[mt][nt][0]), "+f"(acc[mt][nt][1]),
                          "+f"(acc[mt][nt][2]), "+f"(acc[mt][nt][3])
                        : "r"(a[mt][0]), "r"(a[mt][1]), "r"(a[mt][2]), "r"(a[mt][3]),
                          "r"(b[nt][0]), "r"(b[nt][1]));
                }
        }
        __syncthreads();
        if (it + 2 < nIter) prefetch(it + 2, buf);
        cp_commit();
    }

    // Epilogue
#pragma unroll
    for (int mt = 0; mt < MT; mt++) {
#pragma unroll
        for (int nt = 0; nt < NT; nt++) {
            int row0 = rowBase + m_base + mt * 16 + g;
            int col  = colBase + n_base + nt * 8 + 2 * tg;
            float2 v0 = make_float2(acc[mt][nt][0], acc[mt][nt][1]);
            float2 v1 = make_float2(acc[mt][nt][2], acc[mt][nt][3]);
            if constexpr (BIAS) {
                float2 bv = *(const float2*)(bias + col);
                v0.x += bv.x; v0.y += bv.y;
                v1.x += bv.x; v1.y += bv.y;
            }
            if constexpr (SCALE) {
                float s0 = (row0 < M)     ? g_dinv[row0]     : 0.f;
                float s1 = (row0 + 8 < M) ? g_dinv[row0 + 8] : 0.f;
                v0.x *= s0; v0.y *= s0;
                v1.x *= s1; v1.y *= s1;
            }
            if constexpr (OUT_HALF) {
                __half* C = (__half*)Cv;
                if (row0 < M)
                    *(__half2*)(C + (size_t)row0 * N + col) = __floats2half2_rn(v0.x, v0.y);
                if (row0 + 8 < M)
                    *(__half2*)(C + (size_t)(row0 + 8) * N + col) = __floats2half2_rn(v1.x, v1.y);
            } else {
                float* C = (float*)Cv;
                if (row0 < M)     *(float2*)(C + (size_t)row0 * N + col) = v0;
                if (row0 + 8 < M) *(float2*)(C + (size_t)(row0 + 8) * N + col) = v1;
            }
        }
    }
}

// ---------------- Gather aggregation (warp per node), pre-scaled table -------
// xw rows are pre-scaled by dinv[row]. out = relu(di * (xw[i] + sum_s xw[s]) + bias)
__global__ void aggregate_kernel(const __half* __restrict__ xw,
                                 const float* __restrict__ bias,
                                 __half* __restrict__ out) {
    int warp = (blockIdx.x * blockDim.x + threadIdx.x) >> 5;
    int lane = threadIdx.x & 31;
    if (warp >= NN) return;
    int i = warp;

    float di = g_dinv[i];

    float acc[2][8];
    {
        const uint4* xrow = (const uint4*)(xw + (size_t)i * HD);
#pragma unroll
        for (int c = 0; c < 2; c++) {
            uint4 v = xrow[lane + 32 * c];
            const __half2* h2 = (const __half2*)&v;
#pragma unroll
            for (int q = 0; q < 4; q++) {
                float2 f = __half22float2(h2[q]);
                acc[c][2 * q + 0] = f.x;
                acc[c][2 * q + 1] = f.y;
            }
        }
    }

    int beg = g_off[i];
    int cnt = g_counts[i];
    for (int t = 0; t < cnt; t++) {
        int s = g_csr_src[beg + t];
        const uint4* srow = (const uint4*)(xw + (size_t)s * HD);
        uint4 v0 = srow[lane];
        uint4 v1 = srow[lane + 32];
#pragma unroll
        for (int c = 0; c < 2; c++) {
            uint4 v = c ? v1 : v0;
            const __half2* h2 = (const __half2*)&v;
#pragma unroll
            for (int q = 0; q < 4; q++) {
                float2 f = __half22float2(h2[q]);
                acc[c][2 * q + 0] += f.x;
                acc[c][2 * q + 1] += f.y;
            }
        }
    }

#pragma unroll
    for (int c = 0; c < 2; c++) {
        const float4* b4 = (const float4*)(bias + 8 * (lane + 32 * c));
        float4 b0 = b4[0], b1 = b4[1];
        float r0 = fmaxf(fmaf(acc[c][0], di, b0.x), 0.f);
        float r1 = fmaxf(fmaf(acc[c][1], di, b0.y), 0.f);
        float r2 = fmaxf(fmaf(acc[c][2], di, b0.z), 0.f);
        float r3 = fmaxf(fmaf(acc[c][3], di, b0.w), 0.f);
        float r4 = fmaxf(fmaf(acc[c][4], di, b1.x), 0.f);
        float r5 = fmaxf(fmaf(acc[c][5], di, b1.y), 0.f);
        float r6 = fmaxf(fmaf(acc[c][6], di, b1.z), 0.f);
        float r7 = fmaxf(fmaf(acc[c][7], di, b1.w), 0.f);
        __half2 h0 = __floats2half2_rn(r0, r1);
        __half2 h1 = __floats2half2_rn(r2, r3);
        __half2 h2 = __floats2half2_rn(r4, r5);
        __half2 h3 = __floats2half2_rn(r6, r7);
        uint4 q;
        q.x = *(unsigned*)&h0; q.y = *(unsigned*)&h1;
        q.z = *(unsigned*)&h2; q.w = *(unsigned*)&h3;
        *(uint4*)(out + (size_t)i * HD + 8 * (lane + 32 * c)) = q;
    }
}

// ---------------- Launch -----------------------------------------------------
extern "C" void kernel_launch(void* const* d_in, const int* in_sizes, int n_in,
                              void* d_out, int out_size) {
    const float* x  = (const float*)d_in[0];
    const int*   ei = (const int*)d_in[1];
    const float* W1 = (const float*)d_in[2];
    const float* b1 = (const float*)d_in[3];
    const float* W2 = (const float*)d_in[4];
    const float* b2 = (const float*)d_in[5];
    const float* Wl = (const float*)d_in[6];
    const float* bl = (const float*)d_in[7];
    float* out = (float*)d_out;

    __half *x16, *w1t, *w2t, *wlt, *xw, *h;
    cudaGetSymbolAddress((void**)&x16, g_x16);
    cudaGetSymbolAddress((void**)&w1t, g_w1t);
    cudaGetSymbolAddress((void**)&w2t, g_w2t);
    cudaGetSymbolAddress((void**)&wlt, g_wlt);
    cudaGetSymbolAddress((void**)&xw,  g_xw);
    cudaGetSymbolAddress((void**)&h,   g_h);

    // Graph prep + operand conversion
    detect_kernel<<<1, 256>>>(ei);
    zero_counts_kernel<<<(NN + 255) / 256, 256>>>();
    convert_edges_kernel<<<(EE + 255) / 256, 256>>>(ei);
    dinv_kernel<<<(NN + 255) / 256, 256>>>();
    scan1_kernel<<<SCAN_NBLK, SCAN_BLK>>>();
    scan2_kernel<<<1, 32>>>();
    scan3_kernel<<<SCAN_NBLK, SCAN_BLK>>>();
    scatter_kernel<<<(EE + 255) / 256, 256>>>();
    convert_x_kernel<<<(NN * IND / 4 + 255) / 256, 256>>>(x);
    transpose_w_kernel<<<(IND * HD + 255) / 256, 256>>>(w1t, W1, IND, HD);
    transpose_w_kernel<<<(HD * HD + 255) / 256, 256>>>(w2t, W2, HD, HD);
    transpose_w_kernel<<<(HD * OUTD + 255) / 256, 256>>>(wlt, Wl, HD, OUTD);

    // Layer 1: xw = fp16(dinv .* (x @ W1)) ; h = fp16(relu(di*agg + b1))
    {
        dim3 grid(HD / 128, (NN + 127) / 128);
        h_gemm_kernel<128, 128, 2, 4, true, false, true><<<grid, 256>>>(x16, w1t, nullptr, xw, NN, HD, IND);
        aggregate_kernel<<<(NN * 32 + 255) / 256, 256>>>(xw, b1, h);
    }
    // Layer 2
    {
        dim3 grid(HD / 128, (NN + 127) / 128);
        h_gemm_kernel<128, 128, 2, 4, true, false, true><<<grid, 256>>>(h, w2t, nullptr, xw, NN, HD, HD);
        aggregate_kernel<<<(NN * 32 + 255) / 256, 256>>>(xw, b2, h);
    }
    // Output: out = h @ Wl + bl (fp32)
    {
        dim3 grid(OUTD / 64, (NN + 127) / 128);
        h_gemm_kernel<128, 64, 2, 2, false, true, false><<<grid, 128>>>(h, wlt, bl, out, NN, OUTD, HD);
    }
}